// round 17
// baseline (speedup 1.0000x reference)
#include <cuda_runtime.h>
#include <math.h>
#include <stdint.h>

// FootAndBall ball-detection post-process — two kernels + PDL overlap.
//  in : [16, 2, 540, 960] fp32 logits
//  out: [16, 100, 5] fp32 (x1,y1,x2,y2,score), score desc (idx asc on ties).
//
//  K1 detect : d = x1-x0 (NMS on d == NMS on softmax prob, monotone).
//    Streaming float4 NMS, groups of 2 rows double-buffered, ONE wave
//    (grid 480, 4 blocks/SM). Warp-aggregated queue emission; deferred
//    histogram; TWO-LEVEL block-local top-100 cut (24-bit threshold) filters
//    to ~110/block before ONE contiguous per-batch flush. Queue overflow
//    falls back to direct unfiltered append (superset -> still correct).
//    Ends with cudaTriggerProgrammaticLaunchCompletion() — all candidate
//    writes and counter atomics precede the trigger.
//  K2 select : launched with PROGRAMMATIC STREAM SERIALIZATION (PDL): its
//    launch ramp + smem-zero prolog overlap detect's tail; it then calls
//    cudaGridDependencySynchronize() before reading g_cnt/g_cand. R14-R16
//    showed select's interior work is ~2us while the kernel costs ~12.6us —
//    the residue is launch/prolog, which PDL hides under detect.
//    Register-burst select, two-level cut, exact (p desc, idx asc) rank.
//  __device__ globals start zero-initialized; K2 restores zeros.

#define BB   16
#define HH   540
#define WW   960
#define HWSZ (HH * WW)
#define KK   100

#define NT    256                 // detect threads per block (8 warps)
#define RPB   18                  // rows per block; 540 = 30 * 18
#define NBY   30                  // blocks per batch
#define QC    2304                // block smem queue entries (18 KB)
#define HB    4096                // histogram bins (12 bits per level)
#define CAP   2048                // select survivor capacity (expected ~150)
#define CAPG  65536               // per-batch global candidate capacity
#define RPT   16                  // select: candidates per thread (512*16=8192)

__device__ int    g_cnt [BB];
__device__ float2 g_cand[BB][CAPG];

// ---------------------------------------------------------------------------
// Exact softmax channel-1 prob from d = fl(x1-x0). Matches jax.nn.softmax:
// one exp arg is exactly 0 and fl(x0-x1) == -d exactly. (rel_err ~1e-12.)
// ---------------------------------------------------------------------------
__device__ __forceinline__ float prob_from_d(float d) {
#ifdef __FAST_MATH__
    double dd = (double)d;
    double p = (d >= 0.0f) ? (1.0 / (exp(-dd) + 1.0))
                           : (exp(dd) / (exp(dd) + 1.0));
    return (float)p;
#else
    if (d >= 0.0f) { float e0 = expf(-d); return 1.0f / (e0 + 1.0f); }
    else           { float e1 = expf(d);  return e1 / (1.0f + e1);  }
#endif
}

// Order-preserving bit flip: float compare == unsigned compare after flip.
__device__ __forceinline__ unsigned fflip(float f) {
    unsigned u = __float_as_uint(f);
    return u ^ (((unsigned)((int)u >> 31)) | 0x80000000u);
}

// ---------------------------------------------------------------------------
// Log-parallel cut over a 4096-bin smem histogram (256 threads).
// Finds smallest bin c with count(bin >= c) >= K; writes *s_cutbin = c and
// *s_above = count(bin > c). If total < K, leaves both untouched (caller
// pre-zeroes -> keep-everything fallback).
// ---------------------------------------------------------------------------
__device__ __forceinline__ void cut_scan256x(const int* __restrict__ hist,
                                             int* __restrict__ s_wtot,
                                             int* __restrict__ s_cutbin,
                                             int* __restrict__ s_above,
                                             int K, int t) {
    const int lane = t & 31;
    const int w    = t >> 5;
    const int seg  = 255 - t;                // descending bin order
    int val = 0;
    const int4* h4 = (const int4*)(hist + seg * 16);
    #pragma unroll
    for (int j = 0; j < 4; j++) { int4 a = h4[j]; val += a.x + a.y + a.z + a.w; }

    int incl = val;
    #pragma unroll
    for (int sh = 1; sh < 32; sh <<= 1) {
        int n = __shfl_up_sync(0xffffffffu, incl, sh);
        if (lane >= sh) incl += n;
    }
    if (lane == 31) s_wtot[w] = incl;
    __syncthreads();
    if (t < 8) {
        int v = s_wtot[t];
        int inc = v;
        #pragma unroll
        for (int sh = 1; sh < 8; sh <<= 1) {
            int n = __shfl_up_sync(0x000000ffu, inc, sh);
            if (t >= sh) inc += n;
        }
        s_wtot[t] = inc - v;
    }
    __syncthreads();
    int excl = incl - val + s_wtot[w];       // count strictly above seg
    if (excl < K && excl + val >= K) {       // unique boundary thread
        int above = excl;
        int cut = seg * 16;
        #pragma unroll
        for (int c = seg * 16 + 15; c >= seg * 16; c--) {
            int hv = hist[c];
            if (above + hv >= K) { cut = c; break; }
            above += hv;
        }
        *s_cutbin = cut;
        *s_above  = above;
    }
}

// 512-thread variant (8 bins per thread) for the select kernel.
__device__ __forceinline__ void cut_scan512x(const int* __restrict__ hist,
                                             int* __restrict__ s_wtot,
                                             int* __restrict__ s_cutbin,
                                             int* __restrict__ s_above,
                                             int K, int t) {
    const int lane = t & 31;
    const int w    = t >> 5;
    const int seg  = 511 - t;
    int val = 0;
    const int4* h4 = (const int4*)(hist + seg * 8);
    #pragma unroll
    for (int j = 0; j < 2; j++) { int4 a = h4[j]; val += a.x + a.y + a.z + a.w; }

    int incl = val;
    #pragma unroll
    for (int sh = 1; sh < 32; sh <<= 1) {
        int n = __shfl_up_sync(0xffffffffu, incl, sh);
        if (lane >= sh) incl += n;
    }
    if (lane == 31) s_wtot[w] = incl;
    __syncthreads();
    if (t < 16) {
        int v = s_wtot[t];
        int inc = v;
        #pragma unroll
        for (int sh = 1; sh < 16; sh <<= 1) {
            int n = __shfl_up_sync(0x0000ffffu, inc, sh);
            if (t >= sh) inc += n;
        }
        s_wtot[t] = inc - v;
    }
    __syncthreads();
    int excl = incl - val + s_wtot[w];
    if (excl < K && excl + val >= K) {
        int above = excl;
        int cut = seg * 8;
        #pragma unroll
        for (int c = seg * 8 + 7; c >= seg * 8; c--) {
            int hv = hist[c];
            if (above + hv >= K) { cut = c; break; }
            above += hv;
        }
        *s_cutbin = cut;
        *s_above  = above;
    }
}

// ---------------------------------------------------------------------------
// K1: streaming NMS (groups of 2, double buffered) + warp-aggregated emit +
// two-level cut + filtered flush. Grid (1, 30, 16), block 256.
// ---------------------------------------------------------------------------
__global__ __launch_bounds__(NT) void detect_kernel(const float* __restrict__ in) {
    __shared__ __align__(16) int shist[HB];  // 16 KB
    __shared__ float2 s_q[QC];               // 18 KB
    __shared__ int    s_wtot[8];
    __shared__ int    s_cb, s_ab, s_rb, s_du;
    __shared__ int    s_qcnt, s_keep, s_gbase;

    const int b    = blockIdx.z;
    const int by   = blockIdx.y;
    const int tid  = threadIdx.x;
    const int w    = tid >> 5;
    const int lane = tid & 31;

    const int  c0     = w * 120 - 4 + 4 * lane;          // lane's first column
    const bool colok  = ((unsigned)c0 < (unsigned)WW);
    const int  cc     = colok ? c0 : 0;                  // clamped load column
    const bool laneok = (lane >= 1) && (lane <= 30);
    const unsigned lmask = (1u << lane) - 1u;
    const int  r0     = by * RPB;

    if (tid == 0) { s_qcnt = 0; s_keep = 0; s_cb = 0; s_ab = 0; s_rb = 0; s_du = 0; }
    __syncthreads();

    const float* __restrict__ p0 = in + (size_t)b * 2 * HWSZ;
    const float* __restrict__ p1 = p0 + HWSZ;
    int*    __restrict__ gctr = &g_cnt[b];
    float2* __restrict__ gcd  = g_cand[b];

    #define LDROW(R, A, Bv) {                                                  \
        int _rr = (R) < 0 ? 0 : ((R) >= HH ? HH - 1 : (R));                    \
        size_t _o = (size_t)_rr * WW + cc;                                     \
        A  = __ldg(reinterpret_cast<const float4*>(p0 + _o));                  \
        Bv = __ldg(reinterpret_cast<const float4*>(p1 + _o)); }

    #define LOADG(BUF, BASE) {                                                 \
        LDROW((BASE),     sa[BUF][0], sb[BUF][0])                              \
        LDROW((BASE) + 1, sa[BUF][1], sb[BUF][1]) }

    #define CVT(A, Bv, R, D) {                                                 \
        if (colok && ((unsigned)(R) < (unsigned)HH))                            \
            D = make_float4(Bv.x - A.x, Bv.y - A.y, Bv.z - A.z, Bv.w - A.w);    \
        else                                                                    \
            D = make_float4(-INFINITY, -INFINITY, -INFINITY, -INFINITY); }

    #define H3MAX4(D, HM) {                                                    \
        float _dl = __shfl_up_sync(0xffffffffu, (D).w, 1);                      \
        float _dr = __shfl_down_sync(0xffffffffu, (D).x, 1);                    \
        (HM).x = fmaxf(_dl,   fmaxf((D).x, (D).y));                             \
        (HM).y = fmaxf((D).x, fmaxf((D).y, (D).z));                             \
        (HM).z = fmaxf((D).y, fmaxf((D).z, (D).w));                             \
        (HM).w = fmaxf((D).z, fmaxf((D).w, _dr)); }

    // Queue put with global overflow fallback (unfiltered -> superset, OK).
    #define QPUT(P, V, I) {                                                    \
        float2 _v = make_float2(V, __int_as_float(I));                          \
        if ((P) < QC) s_q[P] = _v;                                              \
        else { int _g = atomicAdd(gctr, 1); if (_g < CAPG) gcd[_g] = _v; } }

    // Warp-aggregated emission: 4 ballots, ONE s_qcnt atomic per (warp,row).
    #define EMITROW(DC, HA, HBv, HC, R) {                                      \
        float _m0 = fmaxf((HA).x, fmaxf((HBv).x, (HC).x));                     \
        float _m1 = fmaxf((HA).y, fmaxf((HBv).y, (HC).y));                     \
        float _m2 = fmaxf((HA).z, fmaxf((HBv).z, (HC).z));                     \
        float _m3 = fmaxf((HA).w, fmaxf((HBv).w, (HC).w));                     \
        bool _k0 = laneok && ((DC).x >= _m0);                                  \
        bool _k1 = laneok && ((DC).y >= _m1);                                  \
        bool _k2 = laneok && ((DC).z >= _m2);                                  \
        bool _k3 = laneok && ((DC).w >= _m3);                                  \
        unsigned _b0 = __ballot_sync(0xffffffffu, _k0);                        \
        unsigned _b1 = __ballot_sync(0xffffffffu, _k1);                        \
        unsigned _b2 = __ballot_sync(0xffffffffu, _k2);                        \
        unsigned _b3 = __ballot_sync(0xffffffffu, _k3);                        \
        int _n0 = __popc(_b0), _n1 = __popc(_b1);                              \
        int _n2 = __popc(_b2), _n3 = __popc(_b3);                              \
        int _nc = _n0 + _n1 + _n2 + _n3;                                       \
        if (_nc) {                                                             \
            int _base = 0;                                                     \
            if (lane == 0) _base = atomicAdd(&s_qcnt, _nc);                    \
            _base = __shfl_sync(0xffffffffu, _base, 0);                        \
            int _ib = (R) * WW + c0;                                           \
            if (_k0) QPUT(_base + __popc(_b0 & lmask), (DC).x, _ib)            \
            if (_k1) QPUT(_base + _n0 + __popc(_b1 & lmask), (DC).y, _ib + 1)  \
            if (_k2) QPUT(_base + _n0 + _n1 + __popc(_b2 & lmask),             \
                          (DC).z, _ib + 2)                                     \
            if (_k3) QPUT(_base + _n0 + _n1 + _n2 + __popc(_b3 & lmask),       \
                          (DC).w, _ib + 3)                                     \
        } }

    // --- Streaming NMS: 18 rows as 9 groups of 2, double-buffered loads ----
    {
        float4 sa[2][2], sb[2][2];
        float4 hmA, hmB, dB;
        {
            float4 xa, xb, ya, yb, dm;
            LDROW(r0 - 1, xa, xb)
            LDROW(r0, ya, yb)
            LOADG(0, r0 + 1)                 // rows r0+1, r0+2 (early)
            LOADG(1, r0 + 3)                 // rows r0+3, r0+4 (early)
            CVT(xa, xb, r0 - 1, dm)  H3MAX4(dm, hmA)
            CVT(ya, yb, r0, dB)      H3MAX4(dB, hmB)
        }
        #pragma unroll
        for (int k = 0; k < 9; k++) {
            const int buf = k & 1;
            float4 d1, d2, h1, h2;
            CVT(sa[buf][0], sb[buf][0], r0 + 2 * k + 1, d1)  H3MAX4(d1, h1)
            CVT(sa[buf][1], sb[buf][1], r0 + 2 * k + 2, d2)  H3MAX4(d2, h2)
            if (k < 7) LOADG(buf, r0 + 2 * k + 5)   // refill for iter k+2
            EMITROW(dB, hmA, hmB, h1, r0 + 2 * k)
            EMITROW(d1, hmB, h1, h2, r0 + 2 * k + 1)
            hmA = h1; hmB = h2; dB = d2;
        }
    }
    __syncthreads();

    const int qn = min(s_qcnt, QC);

    // --- Deferred histogram over queue members ------------------------------
    #pragma unroll
    for (int i = tid; i < HB; i += NT) shist[i] = 0;
    __syncthreads();
    for (int i = tid; i < qn; i += NT)
        atomicAdd(&shist[fflip(s_q[i].x) >> 20], 1);
    __syncthreads();

    // --- Two-level block-local top-100 cut ----------------------------------
    cut_scan256x(shist, s_wtot, &s_cb, &s_ab, KK, tid);
    __syncthreads();
    const int cb = s_cb, ab = s_ab;

    #pragma unroll
    for (int i = tid; i < HB; i += NT) shist[i] = 0;   // re-zero for refine
    __syncthreads();
    for (int i = tid; i < qn; i += NT) {
        unsigned f = fflip(s_q[i].x);
        if ((int)(f >> 20) == cb) atomicAdd(&shist[(f >> 8) & 0xFFFu], 1);
    }
    __syncthreads();
    cut_scan256x(shist, s_wtot, &s_rb, &s_du, KK - ab, tid);
    __syncthreads();
    const unsigned bthr = ((unsigned)cb << 20) | ((unsigned)s_rb << 8);

    // --- Filtered contiguous flush of the queue -----------------------------
    int cnt = 0;
    for (int i = tid; i < qn; i += NT)
        cnt += (fflip(s_q[i].x) >= bthr);
    if (cnt) atomicAdd(&s_keep, cnt);
    __syncthreads();
    if (tid == 0) {
        s_gbase = (s_keep > 0) ? atomicAdd(gctr, s_keep) : 0;
        s_keep = 0;
    }
    __syncthreads();
    for (int i = tid; i < qn; i += NT) {
        float2 v = s_q[i];
        if (fflip(v.x) >= bthr) {
            int p = s_gbase + atomicAdd(&s_keep, 1);
            if (p < CAPG) gcd[p] = v;
        }
    }

    // All candidate writes + counter atomics above precede this trigger; PDL
    // guarantees the secondary kernel (post grid-sync) sees them.
    cudaTriggerProgrammaticLaunchCompletion();
}

// ---------------------------------------------------------------------------
// K2: register-burst per-batch top-100 with two-level cut. Grid BB, block 512.
// Launched with PDL: prolog (smem zero) overlaps detect; grid-dependency sync
// before any read of detect's outputs.
// ---------------------------------------------------------------------------
__global__ __launch_bounds__(512) void select_kernel(float* __restrict__ out) {
    __shared__ __align__(16) int shist[HB];  // 16 KB
    __shared__ int      s_wtot[16];
    __shared__ int      s_cb, s_ab, s_rb, s_du;
    __shared__ int      s_count;
    __shared__ float    s_d[CAP];            // 8 KB (d, overwritten by p)
    __shared__ int      s_i[CAP];            // 8 KB

    const int b = blockIdx.x;
    const int t = threadIdx.x;

    // ---- Prolog: runs concurrently with detect's tail (PDL) ----
    {   // vectorized smem hist zero
        int4* h4 = (int4*)shist;
        h4[t]       = make_int4(0, 0, 0, 0);
        h4[t + 512] = make_int4(0, 0, 0, 0);
    }
    if (t == 0) { s_cb = 0; s_ab = 0; s_rb = 0; s_du = 0; s_count = 0; }

    // ---- Wait for detect's trigger + memory visibility ----
    cudaGridDependencySynchronize();

    const int n = min(g_cnt[b], CAPG);
    if (t == 0) g_cnt[b] = 0;               // reset for next graph replay
    const float2* __restrict__ cd = g_cand[b];

    // ---- One unpredicated load burst ----
    float2 v[RPT];
    #pragma unroll
    for (int j = 0; j < RPT; j++) {
        int idx = t + j * 512;
        int ii  = (idx < n) ? idx : 0;       // clamp keeps the load legal
        v[j] = __ldg(cd + ii);
    }
    __syncthreads();                          // hist zero complete

    // ---- Coarse histogram from registers ----
    #pragma unroll
    for (int j = 0; j < RPT; j++)
        if (t + j * 512 < n)
            atomicAdd(&shist[fflip(v[j].x) >> 20], 1);
    for (int i = 512 * RPT + t; i < n; i += 512)      // rare overflow
        atomicAdd(&shist[fflip(cd[i].x) >> 20], 1);
    __syncthreads();

    cut_scan512x(shist, s_wtot, &s_cb, &s_ab, KK, t);
    __syncthreads();
    const int cb = s_cb, ab = s_ab;

    // ---- Refine: histogram of bits [8:20) inside the cut bin ----
    {
        int4* h4 = (int4*)shist;
        h4[t]       = make_int4(0, 0, 0, 0);
        h4[t + 512] = make_int4(0, 0, 0, 0);
    }
    __syncthreads();
    #pragma unroll
    for (int j = 0; j < RPT; j++) {
        if (t + j * 512 < n) {
            unsigned f = fflip(v[j].x);
            if ((int)(f >> 20) == cb) atomicAdd(&shist[(f >> 8) & 0xFFFu], 1);
        }
    }
    for (int i = 512 * RPT + t; i < n; i += 512) {    // rare overflow
        unsigned f = fflip(cd[i].x);
        if ((int)(f >> 20) == cb) atomicAdd(&shist[(f >> 8) & 0xFFFu], 1);
    }
    __syncthreads();
    cut_scan512x(shist, s_wtot, &s_rb, &s_du, KK - ab, t);
    __syncthreads();
    const unsigned thr = ((unsigned)cb << 20) | ((unsigned)s_rb << 8);

    // ---- Collect survivors from registers (C ~ 110-200) ----
    #pragma unroll
    for (int j = 0; j < RPT; j++) {
        if (t + j * 512 < n && fflip(v[j].x) >= thr) {
            int pos = atomicAdd(&s_count, 1);
            if (pos < CAP) { s_d[pos] = v[j].x; s_i[pos] = __float_as_int(v[j].y); }
        }
    }
    for (int i = 512 * RPT + t; i < n; i += 512) {    // rare overflow
        float2 vv = cd[i];
        if (fflip(vv.x) >= thr) {
            int pos = atomicAdd(&s_count, 1);
            if (pos < CAP) { s_d[pos] = vv.x; s_i[pos] = __float_as_int(vv.y); }
        }
    }
    __syncthreads();

    const int C = min(s_count, CAP);

    // ---- Exact p in place, then exact stable rank: p desc, idx asc ----
    for (int e = t; e < C; e += 512) s_d[e] = prob_from_d(s_d[e]);
    __syncthreads();

    for (int e = t; e < C; e += 512) {
        const float p  = s_d[e];
        const int   id = s_i[e];
        int rank = 0;
        for (int j = 0; j < C; j++) {
            float pj = s_d[j];
            rank += (pj > p) || (pj == p && s_i[j] < id);
        }
        if (rank < KK) {
            int ww = id % WW;
            int hh = id / WW;
            float xc = (float)ww * 4.0f + 1.5f;
            float yc = (float)hh * 4.0f + 1.5f;
            float* o = out + ((size_t)b * KK + rank) * 5;
            o[0] = xc - 10.0f;
            o[1] = yc - 10.0f;
            o[2] = xc + 10.0f;
            o[3] = yc + 10.0f;
            o[4] = p;
        }
    }
}

// ---------------------------------------------------------------------------
extern "C" void kernel_launch(void* const* d_in, const int* in_sizes, int n_in,
                              void* d_out, int out_size) {
    const float* in = (const float*)d_in[0];
    float* out = (float*)d_out;

    dim3 grid(1, NBY, BB);                    // (1, 30, 16) = 480 blocks
    detect_kernel<<<grid, NT>>>(in);

    // PDL launch: select's prolog overlaps detect's tail.
    cudaLaunchConfig_t cfg = {};
    cfg.gridDim  = dim3(BB, 1, 1);
    cfg.blockDim = dim3(512, 1, 1);
    cudaLaunchAttribute attrs[1];
    attrs[0].id = cudaLaunchAttributeProgrammaticStreamSerialization;
    attrs[0].val.programmaticStreamSerializationAllowed = 1;
    cfg.attrs    = attrs;
    cfg.numAttrs = 1;
    cudaLaunchKernelEx(&cfg, select_kernel, out);
}